// round 1
// baseline (speedup 1.0000x reference)
#include <cuda_runtime.h>
#include <cuda_bf16.h>

// Problem constants (match reference)
#define NE    32      // electrons (16 up + 16 down)
#define NNUC  8       // nuclei
#define NCHI  8       // e-N poly order
#define NU    8       // e-e poly order
#define NTYPES 3

__global__ __launch_bounds__(256, 8)
void jastrow_kernel(
    const float* __restrict__ elec,     // [B, 32, 32]
    const float* __restrict__ nuc,      // [B, 32, 8]
    const float* __restrict__ alpha,    // [8]
    const float* __restrict__ beta,     // [3, 8]
    const float* __restrict__ Zarr,     // [8]
    const float* __restrict__ Lchi,     // [3]
    const float* __restrict__ Lu_p,     // [1]
    const int*   __restrict__ type_idx, // [8]
    float* __restrict__ out)            // [B]
{
    __shared__ float s_beta[NNUC][NCHI];   // per-nucleus gathered coefs
    __shared__ float s_lin[NNUC];          // cusp linear coef per nucleus
    __shared__ float s_L[NNUC];            // cutoff per nucleus
    __shared__ float s_alpha[NU];
    __shared__ float s_Lu;
    __shared__ float s_slope_same, s_slope_diff;
    __shared__ float s_warp[8];

    const int t = threadIdx.x;
    const int b = blockIdx.x;

    // ---- per-block constant setup (tiny; a few threads only) ----
    if (t < NNUC) {
        int ty = type_idx[t];
        float L = Lchi[ty];
        s_L[t] = L;
        #pragma unroll
        for (int l = 0; l < NCHI; ++l) s_beta[t][l] = beta[ty * NCHI + l];
        float negL3 = -(L * L * L);          // (-L)^3
        // lin_coef = -Z/(-L)^3 + beta0*3/L
        s_lin[t] = -Zarr[t] / negL3 + s_beta[t][0] * 3.0f / L;
    }
    if (t >= 32 && t < 32 + NU) {
        s_alpha[t - 32] = alpha[t - 32];
    }
    if (t == 64) {
        float Lu = Lu_p[0];
        s_Lu = Lu;
        float a0 = alpha[0];
        float negL3 = -(Lu * Lu * Lu);
        s_slope_same = 0.25f / negL3 + a0 * 3.0f / Lu;  // same spin G=0.25
        s_slope_diff = 0.50f / negL3 + a0 * 3.0f / Lu;  // diff spin G=0.5
    }
    __syncthreads();

    float acc = 0.0f;

    // ---- e-N term: 256 elements, one per thread ----
    // dists_nuc layout [B, n, M]: element t -> electron t/8, nucleus t%8.
    // chi value depends only on r and nucleus index; fully coalesced read.
    {
        float r = nuc[(size_t)b * (NE * NNUC) + t];
        int m = t & (NNUC - 1);
        float L = s_L[m];
        if (r < L) {
            float d = r - L;
            float env = d * d * d;               // (r-L)^3, r<L
            // Horner over beta[1..7] for powers r^2..r^8
            float p = s_beta[m][NCHI - 1];
            #pragma unroll
            for (int l = NCHI - 2; l >= 1; --l) p = fmaf(p, r, s_beta[m][l]);
            p = s_beta[m][0] + s_lin[m] * r + r * r * p;
            acc += env * p * (1.0f / (float)NNUC);   // mean over nuclei
        }
    }

    // ---- e-e term: 1024 elements, 4 per thread, upper triangle only ----
    const float* erow = elec + (size_t)b * (NE * NE);
    const float Lu = s_Lu;
    #pragma unroll
    for (int k = 0; k < 4; ++k) {
        int idx = t + k * 256;
        int i = idx >> 5;
        int j = idx & 31;
        if (j > i) {
            float r = erow[idx];
            if (r < Lu) {
                float d = r - Lu;
                float env = d * d * d;
                bool same = (i < 16) == (j < 16);
                float slope = same ? s_slope_same : s_slope_diff;
                float p = s_alpha[NU - 1];
                #pragma unroll
                for (int l = NU - 2; l >= 1; --l) p = fmaf(p, r, s_alpha[l]);
                p = s_alpha[0] + slope * r + r * r * p;
                acc += env * p;
            }
        }
    }

    // ---- block reduction: warp shuffle then 8-lane final ----
    #pragma unroll
    for (int off = 16; off > 0; off >>= 1)
        acc += __shfl_down_sync(0xffffffffu, acc, off);
    if ((t & 31) == 0) s_warp[t >> 5] = acc;
    __syncthreads();
    if (t < 8) {
        float v = s_warp[t];
        #pragma unroll
        for (int off = 4; off > 0; off >>= 1)
            v += __shfl_down_sync(0xffu, v, off);
        if (t == 0) out[b] = v;
    }
}

extern "C" void kernel_launch(void* const* d_in, const int* in_sizes, int n_in,
                              void* d_out, int out_size)
{
    const float* elec  = (const float*)d_in[0];   // [B,32,32]
    const float* nuc   = (const float*)d_in[1];   // [B,32,8]
    const float* alpha = (const float*)d_in[2];   // [8]
    const float* beta  = (const float*)d_in[3];   // [3,8]
    const float* Z     = (const float*)d_in[4];   // [8]
    const float* Lchi  = (const float*)d_in[5];   // [3]
    const float* Lu    = (const float*)d_in[6];   // [1]
    const int*   tidx  = (const int*)  d_in[7];   // [8]
    float* out = (float*)d_out;

    int B = in_sizes[1] / (NE * NNUC);            // 4096

    jastrow_kernel<<<B, 256>>>(elec, nuc, alpha, beta, Z, Lchi, Lu, tidx, out);
}

// round 2
// speedup vs baseline: 1.1379x; 1.1379x over previous
#include <cuda_runtime.h>
#include <cuda_bf16.h>

#define NE    32
#define NNUC  8
#define NCHI  8
#define NU    8
#define WPB   8      // walkers (warps) per block

__global__ __launch_bounds__(256, 6)
void jastrow_kernel(
    const float4* __restrict__ elec4,   // [B, 256]  (32x32 floats as float4)
    const float4* __restrict__ nuc4,    // [B, 64]   (32x8 floats as float4)
    const float* __restrict__ alpha,    // [8]
    const float* __restrict__ beta,     // [3, 8]
    const float* __restrict__ Zarr,     // [8]
    const float* __restrict__ Lchi,     // [3]
    const float* __restrict__ Lu_p,     // [1]
    const int*   __restrict__ type_idx, // [8]
    float* __restrict__ out)            // [B]
{
    __shared__ float s_beta[NNUC][NCHI];
    __shared__ float s_lin[NNUC];
    __shared__ float s_L[NNUC];
    __shared__ float s_alpha[NU];
    __shared__ float s_Lu;
    __shared__ float s_slope_same, s_slope_diff;

    const int t    = threadIdx.x;
    const int lane = t & 31;
    const int w    = t >> 5;
    const int b    = blockIdx.x * WPB + w;

    // ---- per-block constant setup ----
    if (t < NNUC) {
        int ty = type_idx[t];
        float L = Lchi[ty];
        s_L[t] = L;
        #pragma unroll
        for (int l = 0; l < NCHI; ++l) s_beta[t][l] = beta[ty * NCHI + l];
        float negL3 = -(L * L * L);
        s_lin[t] = -Zarr[t] / negL3 + s_beta[t][0] * 3.0f / L;
    }
    if (t >= 32 && t < 32 + NU) s_alpha[t - 32] = alpha[t - 32];
    if (t == 64) {
        float Lu = Lu_p[0];
        s_Lu = Lu;
        float a0 = alpha[0];
        float negL3 = -(Lu * Lu * Lu);
        s_slope_same = 0.25f / negL3 + a0 * 3.0f / Lu;
        s_slope_diff = 0.50f / negL3 + a0 * 3.0f / Lu;
    }
    __syncthreads();

    // =========================================================
    // Issue ALL loads first (max MLP), then compute.
    // =========================================================

    // e-N: 64 float4 per walker, 2 per lane.
    float4 rn0 = nuc4[(size_t)b * 64 + lane];
    float4 rn1 = nuc4[(size_t)b * 64 + 32 + lane];

    // e-e: 256 float4 per walker, 8 per lane. Skip float4s entirely in
    // the lower triangle (max j <= i).
    const float4* erow = elec4 + (size_t)b * 256;
    const int i_off = lane >> 3;         // contribution of lane to row index
    const int jb    = (lane & 7) * 4;    // first j covered by this lane's float4
    float4 re[8];
    #pragma unroll
    for (int k = 0; k < 8; ++k) {
        int i = k * 4 + i_off;
        if (jb + 3 > i) re[k] = erow[k * 32 + lane];
        else            re[k] = make_float4(0.f, 0.f, 0.f, 0.f);
    }

    float acc = 0.0f;

    // ---- e-N compute ----
    // float4 element p at flat idx (it*32+lane)*4+p -> nucleus m=(lane&1)*4+p
    {
        const int mb = (lane & 1) * 4;
        const float rs[8] = { rn0.x, rn0.y, rn0.z, rn0.w, rn1.x, rn1.y, rn1.z, rn1.w };
        #pragma unroll
        for (int q = 0; q < 8; ++q) {
            int m = mb + (q & 3);
            float r = rs[q];
            float L = s_L[m];
            float d = r - L;
            float env = (r < L) ? d * d * d : 0.0f;
            float p = s_beta[m][NCHI - 1];
            #pragma unroll
            for (int l = NCHI - 2; l >= 1; --l) p = fmaf(p, r, s_beta[m][l]);
            p = s_beta[m][0] + s_lin[m] * r + r * r * p;
            acc = fmaf(env, p * 0.125f, acc);
        }
    }

    // ---- e-e compute ----
    {
        const float Lu = s_Lu;
        const float ssame = s_slope_same, sdiff = s_slope_diff;
        const bool jlow = (jb < 16);     // j group (all 4 j share it, 4-aligned)
        #pragma unroll
        for (int k = 0; k < 8; ++k) {
            int i = k * 4 + i_off;
            float slope = (((i < 16) == jlow) ? ssame : sdiff);
            float rv[4] = { re[k].x, re[k].y, re[k].z, re[k].w };
            #pragma unroll
            for (int p4 = 0; p4 < 4; ++p4) {
                int j = jb + p4;
                float r = rv[p4];
                if (j > i && r < Lu) {
                    float d = r - Lu;
                    float env = d * d * d;
                    float p = s_alpha[NU - 1];
                    #pragma unroll
                    for (int l = NU - 2; l >= 1; --l) p = fmaf(p, r, s_alpha[l]);
                    p = s_alpha[0] + slope * r + r * r * p;
                    acc = fmaf(env, p, acc);
                }
            }
        }
    }

    // ---- warp reduction, lane 0 writes ----
    #pragma unroll
    for (int off = 16; off > 0; off >>= 1)
        acc += __shfl_down_sync(0xffffffffu, acc, off);
    if (lane == 0) out[b] = acc;
}

extern "C" void kernel_launch(void* const* d_in, const int* in_sizes, int n_in,
                              void* d_out, int out_size)
{
    const float4* elec  = (const float4*)d_in[0];
    const float4* nuc   = (const float4*)d_in[1];
    const float* alpha  = (const float*)d_in[2];
    const float* beta   = (const float*)d_in[3];
    const float* Z      = (const float*)d_in[4];
    const float* Lchi   = (const float*)d_in[5];
    const float* Lu     = (const float*)d_in[6];
    const int*   tidx   = (const int*)  d_in[7];
    float* out = (float*)d_out;

    int B = in_sizes[1] / (NE * NNUC);   // 4096

    jastrow_kernel<<<B / WPB, 256>>>(elec, nuc, alpha, beta, Z, Lchi, Lu, tidx, out);
}

// round 3
// speedup vs baseline: 1.4172x; 1.2454x over previous
#include <cuda_runtime.h>
#include <cuda_bf16.h>

#define NE    32
#define NNUC  8
#define NCHI  8
#define NU    8
#define WPB   4      // walkers per block (2 warps each -> 256 threads)

// Flat float4-chunk indices (i*8 + c) of all 136 chunks that touch the strict
// upper triangle (exist j in [4c,4c+3] with j > i) of the 32x32 elec matrix.
static __device__ const unsigned char UPPER_TAB[136] = {
    0,1,2,3,4,5,6,7,
    8,9,10,11,12,13,14,15,
    16,17,18,19,20,21,22,23,
    25,26,27,28,29,30,31,
    33,34,35,36,37,38,39,
    41,42,43,44,45,46,47,
    49,50,51,52,53,54,55,
    58,59,60,61,62,63,
    66,67,68,69,70,71,
    74,75,76,77,78,79,
    82,83,84,85,86,87,
    91,92,93,94,95,
    99,100,101,102,103,
    107,108,109,110,111,
    115,116,117,118,119,
    124,125,126,127,
    132,133,134,135,
    140,141,142,143,
    148,149,150,151,
    157,158,159,
    165,166,167,
    173,174,175,
    181,182,183,
    190,191,
    198,199,
    206,207,
    214,215,
    223,
    231,
    239,
    247
};

__global__ __launch_bounds__(256)
void jastrow_kernel(
    const float4* __restrict__ elec4,   // [B, 256]
    const float4* __restrict__ nuc4,    // [B, 64]
    const float* __restrict__ alpha,    // [8]
    const float* __restrict__ beta,     // [3, 8]
    const float* __restrict__ Zarr,     // [8]
    const float* __restrict__ Lchi,     // [3]
    const float* __restrict__ Lu_p,     // [1]
    const int*   __restrict__ type_idx, // [8]
    float* __restrict__ out)            // [B]
{
    __shared__ float s_beta[NNUC][NCHI];
    __shared__ float s_lin[NNUC];
    __shared__ float s_L[NNUC];
    __shared__ float s_alpha[NU];
    __shared__ float s_Lu, s_slope_same, s_slope_diff;
    __shared__ unsigned char s_tab[136];
    __shared__ float s_part[8];

    const int t    = threadIdx.x;
    const int lane = t & 31;
    const int warp = t >> 5;
    const int wk   = warp >> 1;          // walker within block (0..3)
    const int half = warp & 1;           // which half-warp team
    const int b    = blockIdx.x * WPB + wk;
    const int l    = half * 32 + lane;   // 0..63: lane id within walker team

    // ---- constant setup ----
    if (t < NNUC) {
        int ty = type_idx[t];
        float L = Lchi[ty];
        s_L[t] = L;
        #pragma unroll
        for (int q = 0; q < NCHI; ++q) s_beta[t][q] = beta[ty * NCHI + q];
        float negL3 = -(L * L * L);
        s_lin[t] = -Zarr[t] / negL3 + s_beta[t][0] * 3.0f / L;
    }
    if (t >= 32 && t < 32 + NU) s_alpha[t - 32] = alpha[t - 32];
    if (t == 64) {
        float Lu = Lu_p[0];
        s_Lu = Lu;
        float a0 = alpha[0];
        float negL3 = -(Lu * Lu * Lu);
        s_slope_same = 0.25f / negL3 + a0 * 3.0f / Lu;
        s_slope_diff = 0.50f / negL3 + a0 * 3.0f / Lu;
    }
    if (t < 136) s_tab[t] = UPPER_TAB[t];
    __syncthreads();

    // ---- issue all loads up front ----
    float4 rn = nuc4[(size_t)b * 64 + l];                 // 1 nuc chunk per lane

    const float4* erow = elec4 + (size_t)b * 256;
    int v0 = s_tab[l];
    int v1 = s_tab[l + 64];
    float4 e0 = erow[v0];
    float4 e1 = erow[v1];
    float4 e2;
    int v2 = 0;
    const bool has2 = (l < 136 - 128);                    // lanes 0..7 of team
    if (has2) { v2 = s_tab[128 + l]; e2 = erow[v2]; }

    float acc = 0.0f;

    // ---- e-N: nuc chunk l covers electron l>>1, nuclei (l&1)*4 + p ----
    {
        const int mb = (l & 1) * 4;
        const float rs[4] = { rn.x, rn.y, rn.z, rn.w };
        #pragma unroll
        for (int p4 = 0; p4 < 4; ++p4) {
            int m = mb + p4;
            float r = rs[p4];
            float L = s_L[m];
            float d = r - L;
            float env = (r < L) ? d * d * d : 0.0f;
            float p = s_beta[m][NCHI - 1];
            #pragma unroll
            for (int q = NCHI - 2; q >= 1; --q) p = fmaf(p, r, s_beta[m][q]);
            p = s_beta[m][0] + s_lin[m] * r + r * r * p;
            acc = fmaf(env, p * 0.125f, acc);
        }
    }

    // ---- e-e chunks ----
    const float Lu = s_Lu;
    const float ssame = s_slope_same, sdiff = s_slope_diff;

    auto do_chunk = [&](int v, const float4& e) {
        int i  = v >> 3;
        int jb = (v & 7) * 4;
        float slope = (((i < 16) == (jb < 16)) ? ssame : sdiff);
        float rv[4] = { e.x, e.y, e.z, e.w };
        #pragma unroll
        for (int p4 = 0; p4 < 4; ++p4) {
            int j = jb + p4;
            float r = rv[p4];
            if (j > i && r < Lu) {
                float d = r - Lu;
                float env = d * d * d;
                float p = s_alpha[NU - 1];
                #pragma unroll
                for (int q = NU - 2; q >= 1; --q) p = fmaf(p, r, s_alpha[q]);
                p = s_alpha[0] + slope * r + r * r * p;
                acc = fmaf(env, p, acc);
            }
        }
    };

    do_chunk(v0, e0);
    do_chunk(v1, e1);
    if (has2) do_chunk(v2, e2);

    // ---- reduce: warp shuffle, then combine the two team warps ----
    #pragma unroll
    for (int off = 16; off > 0; off >>= 1)
        acc += __shfl_down_sync(0xffffffffu, acc, off);
    if (lane == 0) s_part[warp] = acc;
    __syncthreads();
    if (t < WPB)
        out[blockIdx.x * WPB + t] = s_part[2 * t] + s_part[2 * t + 1];
}

extern "C" void kernel_launch(void* const* d_in, const int* in_sizes, int n_in,
                              void* d_out, int out_size)
{
    const float4* elec  = (const float4*)d_in[0];
    const float4* nuc   = (const float4*)d_in[1];
    const float* alpha  = (const float*)d_in[2];
    const float* beta   = (const float*)d_in[3];
    const float* Z      = (const float*)d_in[4];
    const float* Lchi   = (const float*)d_in[5];
    const float* Lu     = (const float*)d_in[6];
    const int*   tidx   = (const int*)  d_in[7];
    float* out = (float*)d_out;

    int B = in_sizes[1] / (NE * NNUC);   // 4096

    jastrow_kernel<<<B / WPB, 256>>>(elec, nuc, alpha, beta, Z, Lchi, Lu, tidx, out);
}